// round 7
// baseline (speedup 1.0000x reference)
#include <cuda_runtime.h>
#include <math.h>
#include <stdint.h>

// Problem constants (fixed shapes)
#define Bb   2
#define Ll   2048
#define DMd  2048
#define DIi  4096
#define Nst  64
#define Pd   64
#define Hh   64
#define CONVC 4224
#define PROJC 8384
#define EPSf 1e-6f
#define ML   (Bb*Ll)   // 4096 rows

// ---------------- scratch (device globals; no allocation allowed) ----------
__device__ float g_hs[(size_t)ML * DMd];     // rmsnorm(u), tf32-rounded
__device__ float g_zx[(size_t)ML * PROJC];   // in_proj output
__device__ float g_xc[(size_t)ML * CONVC];   // conv+silu output
__device__ float g_dt[ML * Hh];
__device__ float g_dA[ML * Hh];
__device__ float g_y [(size_t)ML * DIi];     // scan output + D*x
__device__ float g_nr[(size_t)ML * DIi];     // gated rmsnorm output, tf32-rounded
__device__ float g_w1[(size_t)PROJC * DMd];  // in_proj_w tf32-rounded
__device__ float g_w2[(size_t)DMd * DIi];    // out_proj_w tf32-rounded
__device__ float g_pt[(size_t)4 * ML * DMd]; // split-K partials for out_proj

// ====================== PTX helpers =======================================
__device__ __forceinline__ uint32_t smem_u32(const void* p) {
    uint32_t a;
    asm("{ .reg .u64 t; cvta.to.shared.u64 t, %1; cvt.u32.u64 %0, t; }" : "=r"(a) : "l"(p));
    return a;
}
__device__ __forceinline__ void cp16(uint32_t dst, const void* src, int srcsize) {
    asm volatile("cp.async.cg.shared.global [%0], [%1], 16, %2;" :: "r"(dst), "l"(src), "r"(srcsize));
}
#define CP_COMMIT() asm volatile("cp.async.commit_group;" ::: "memory")
#define CP_WAIT(n)  asm volatile("cp.async.wait_group %0;" :: "n"(n) : "memory")

__device__ __forceinline__ void mma_tf32(float* d, const uint32_t* a, const uint32_t* b) {
    asm volatile(
        "mma.sync.aligned.m16n8k8.row.col.f32.tf32.tf32.f32 "
        "{%0,%1,%2,%3}, {%4,%5,%6,%7}, {%8,%9}, {%0,%1,%2,%3};"
        : "+f"(d[0]), "+f"(d[1]), "+f"(d[2]), "+f"(d[3])
        : "r"(a[0]), "r"(a[1]), "r"(a[2]), "r"(a[3]), "r"(b[0]), "r"(b[1]));
}

// ====================== wide tf32 GEMM (mma.sync) ==========================
// C[m,n] = sum_{k in split} A[m,k] * W[n,k]. A:(M,K), W:(N,K), K-major, tf32-rounded.
// CTA tile 128x256x16, 8 warps, warp tile 64x64 (4x8 m16n8k8), 3-stage cp.async.
// gridDim.z = split-K count; partial z written at Cpart + z*ML*Nout.
#define WBM 128
#define WBN 256
#define WBK 16
#define WKP 20                      // padded row pitch in floats
#define A_STG (WBM * WKP)           // floats per A stage
#define B_STG (WBN * WKP)           // floats per B stage
#define SMEM_WIDE (3 * (A_STG + B_STG) * 4)

__global__ __launch_bounds__(256, 1) void gemm_wide(
    const float* __restrict__ A, const float* __restrict__ W,
    float* __restrict__ Cpart, int Nout, int K, int kLen)
{
    extern __shared__ float sm[];
    float* Abase = sm;
    float* Bbase = sm + 3 * A_STG;
    uint32_t sA = smem_u32(Abase);
    uint32_t sB = smem_u32(Bbase);

    int tid = threadIdx.x;
    int warp = tid >> 5, lane = tid & 31;
    int bm = blockIdx.y * WBM, bn = blockIdx.x * WBN;
    int k0base = blockIdx.z * kLen;
    float* C = Cpart + (size_t)blockIdx.z * ((size_t)ML * Nout);

    int wm = (warp >> 2) * 64;   // 0 or 64
    int wn = (warp & 3) * 64;    // 0,64,128,192

    float d[4][8][4];
    #pragma unroll
    for (int i = 0; i < 4; i++)
        #pragma unroll
        for (int j = 0; j < 8; j++)
            #pragma unroll
            for (int f = 0; f < 4; f++) d[i][j][f] = 0.f;

    int NS = kLen / WBK;

    auto load_stage = [&](int s, int buf) {
        int k0 = k0base + s * WBK;
        #pragma unroll
        for (int i = 0; i < 2; i++) {           // A: 512 tasks
            int id = tid + i * 256;
            int r = id >> 2, seg = id & 3;
            cp16(sA + (buf * A_STG + r * WKP + seg * 4) * 4,
                 A + (size_t)(bm + r) * K + k0 + seg * 4, 16);
        }
        #pragma unroll
        for (int i = 0; i < 4; i++) {           // B: 1024 tasks
            int id = tid + i * 256;
            int r = id >> 2, seg = id & 3;
            int ok = (bn + r) < Nout;
            cp16(sB + (buf * B_STG + r * WKP + seg * 4) * 4,
                 W + (size_t)(ok ? (bn + r) : 0) * K + k0 + seg * 4, ok ? 16 : 0);
        }
        CP_COMMIT();
    };

    auto compute = [&](int buf) {
        const float* As = Abase + buf * A_STG;
        const float* Bs = Bbase + buf * B_STG;
        int row = lane >> 2, kq = lane & 3;
        #pragma unroll
        for (int ks = 0; ks < WBK; ks += 8) {
            uint32_t af[4][4], bf[8][2];
            #pragma unroll
            for (int mt = 0; mt < 4; mt++) {
                int r0 = wm + mt * 16 + row;
                af[mt][0] = __float_as_uint(As[r0 * WKP + ks + kq]);
                af[mt][1] = __float_as_uint(As[(r0 + 8) * WKP + ks + kq]);
                af[mt][2] = __float_as_uint(As[r0 * WKP + ks + kq + 4]);
                af[mt][3] = __float_as_uint(As[(r0 + 8) * WKP + ks + kq + 4]);
            }
            #pragma unroll
            for (int nt = 0; nt < 8; nt++) {
                int n0 = wn + nt * 8 + row;
                bf[nt][0] = __float_as_uint(Bs[n0 * WKP + ks + kq]);
                bf[nt][1] = __float_as_uint(Bs[n0 * WKP + ks + kq + 4]);
            }
            #pragma unroll
            for (int mt = 0; mt < 4; mt++)
                #pragma unroll
                for (int nt = 0; nt < 8; nt++)
                    mma_tf32(d[mt][nt], af[mt], bf[nt]);
        }
    };

    load_stage(0, 0);
    load_stage(1, 1);
    for (int s = 0; s < NS; s++) {
        if (s + 1 < NS) { CP_WAIT(1); } else { CP_WAIT(0); }
        __syncthreads();
        if (s + 2 < NS) load_stage(s + 2, (s + 2) % 3);
        compute(s % 3);
    }

    // epilogue
    int row = lane >> 2, kq = lane & 3;
    #pragma unroll
    for (int mt = 0; mt < 4; mt++) {
        int r0 = bm + wm + mt * 16 + row;
        #pragma unroll
        for (int nt = 0; nt < 8; nt++) {
            int c0 = bn + wn + nt * 8 + kq * 2;
            if (c0 < Nout) {
                *(float2*)(C + (size_t)r0 * Nout + c0) =
                    make_float2(d[mt][nt][0], d[mt][nt][1]);
                *(float2*)(C + (size_t)(r0 + 8) * Nout + c0) =
                    make_float2(d[mt][nt][2], d[mt][nt][3]);
            }
        }
    }
}

// ---------------- split-K reduce + residual --------------------------------
__global__ void reduce4_kernel(const float* __restrict__ u, float* __restrict__ out) {
    int i = blockIdx.x * 256 + threadIdx.x;   // < ML*DMd/4
    const float4* p0 = (const float4*)g_pt;
    const float4* p1 = p0 + (size_t)ML * DMd / 4;
    const float4* p2 = p1 + (size_t)ML * DMd / 4;
    const float4* p3 = p2 + (size_t)ML * DMd / 4;
    float4 a = p0[i], b = p1[i], c = p2[i], e = p3[i];
    float4 r = ((const float4*)u)[i];
    float4 o;
    o.x = a.x + b.x + c.x + e.x + r.x;
    o.y = a.y + b.y + c.y + e.y + r.y;
    o.z = a.z + b.z + c.z + e.z + r.z;
    o.w = a.w + b.w + c.w + e.w + r.w;
    ((float4*)out)[i] = o;
}

// ---------------- tf32 rounding pass (weights) -----------------------------
__global__ void tf32_round4(const float4* __restrict__ in, float4* __restrict__ out, int n4) {
    int i = blockIdx.x * 256 + threadIdx.x;
    if (i < n4) {
        float4 v = in[i];
        uint32_t a, b, c, d;
        asm("cvt.rna.tf32.f32 %0, %1;" : "=r"(a) : "f"(v.x));
        asm("cvt.rna.tf32.f32 %0, %1;" : "=r"(b) : "f"(v.y));
        asm("cvt.rna.tf32.f32 %0, %1;" : "=r"(c) : "f"(v.z));
        asm("cvt.rna.tf32.f32 %0, %1;" : "=r"(d) : "f"(v.w));
        float4 o;
        o.x = __uint_as_float(a); o.y = __uint_as_float(b);
        o.z = __uint_as_float(c); o.w = __uint_as_float(d);
        out[i] = o;
    }
}

// ---------------- helpers ----------------
__device__ __forceinline__ float block_sum_256(float v) {
    #pragma unroll
    for (int o = 16; o; o >>= 1) v += __shfl_xor_sync(0xffffffffu, v, o);
    __shared__ float sh[8];
    int w = threadIdx.x >> 5;
    if ((threadIdx.x & 31) == 0) sh[w] = v;
    __syncthreads();
    float s = 0.f;
    #pragma unroll
    for (int i = 0; i < 8; i++) s += sh[i];
    return s;
}
__device__ __forceinline__ float siluf(float x) { return x / (1.f + expf(-x)); }
__device__ __forceinline__ float tf32r(float x) {
    uint32_t r; asm("cvt.rna.tf32.f32 %0, %1;" : "=r"(r) : "f"(x));
    return __uint_as_float(r);
}

// ---------------- 1) input RMSNorm: u (ML,2048) -> g_hs (tf32) -------------
__global__ void rmsnorm_in_kernel(const float* __restrict__ u,
                                  const float* __restrict__ w) {
    int row = blockIdx.x;
    const float* x = u + (size_t)row * DMd;
    float* o = g_hs + (size_t)row * DMd;
    int t = threadIdx.x;
    float v[8];
    float ss = 0.f;
    #pragma unroll
    for (int i = 0; i < 2; i++) {
        float4 p = *(const float4*)(x + t * 4 + i * 1024);
        v[i*4+0]=p.x; v[i*4+1]=p.y; v[i*4+2]=p.z; v[i*4+3]=p.w;
        ss += p.x*p.x + p.y*p.y + p.z*p.z + p.w*p.w;
    }
    float total = block_sum_256(ss);
    float scale = rsqrtf(total / (float)DMd + EPSf);
    #pragma unroll
    for (int i = 0; i < 2; i++) {
        int c = t * 4 + i * 1024;
        float4 q;
        q.x = tf32r(w[c+0] * v[i*4+0] * scale);
        q.y = tf32r(w[c+1] * v[i*4+1] * scale);
        q.z = tf32r(w[c+2] * v[i*4+2] * scale);
        q.w = tf32r(w[c+3] * v[i*4+3] * scale);
        *(float4*)(o + c) = q;
    }
}

// ---------------- 3) causal depthwise conv (K=4) + SiLU --------------------
__global__ void conv_silu_kernel(const float* __restrict__ conv_w,
                                 const float* __restrict__ conv_b) {
    int c  = blockIdx.x * 128 + threadIdx.x;   // 0..4223
    int bl = blockIdx.y;                        // 0..ML-1
    int b = bl >> 11;
    int l = bl & 2047;
    float acc = conv_b[c];
    #pragma unroll
    for (int k = 0; k < 4; k++) {
        int ls = l + k - 3;
        if (ls >= 0)
            acc += g_zx[(size_t)((b << 11) + ls) * PROJC + DIi + c] * conv_w[k * CONVC + c];
    }
    g_xc[(size_t)bl * CONVC + c] = siluf(acc);
}

// ---------------- 4) dt = softplus(raw + bias); dA = exp(-exp(Alog)*dt) ----
__global__ void dt_kernel(const float* __restrict__ dt_bias,
                          const float* __restrict__ A_log) {
    int idx = blockIdx.x * 256 + threadIdx.x;
    int m = idx >> 6;
    int h = idx & 63;
    float x = g_zx[(size_t)m * PROJC + DIi + CONVC + h] + dt_bias[h];
    float sp = (x > 20.f) ? x : log1pf(expf(x));
    g_dt[idx] = sp;
    g_dA[idx] = expf(-expf(A_log[h]) * sp);
}

// ---------------- 5) sequential selective scan -----------------------------
__global__ __launch_bounds__(128) void scan_kernel(const float* __restrict__ Dp) {
    int hh = blockIdx.x, b = blockIdx.y;
    int tid = threadIdx.x;
    int q  = tid & 3;
    int pg = tid >> 2;
    int n0 = q << 4;
    int p0 = pg << 1, p1 = p0 + 1;

    __shared__ float sB[32][64], sC[32][64], sx[32][64];
    __shared__ float sdt[32], sdA[32];

    float h0[16], h1[16];
    #pragma unroll
    for (int i = 0; i < 16; i++) { h0[i] = 0.f; h1[i] = 0.f; }
    float Dh = Dp[hh];

    for (int l0 = 0; l0 < Ll; l0 += 32) {
        __syncthreads();
        for (int j = tid; j < 32 * 64; j += 128) {
            int s = j >> 6, n = j & 63;
            size_t rb = (size_t)((b << 11) + l0 + s) * CONVC;
            sB[s][n] = g_xc[rb + DIi + n];
            sC[s][n] = g_xc[rb + DIi + Nst + n];
            sx[s][n] = g_xc[rb + (hh << 6) + n];
        }
        if (tid < 32) {
            int m = (b << 11) + l0 + tid;
            sdt[tid] = g_dt[m * Hh + hh];
            sdA[tid] = g_dA[m * Hh + hh];
        }
        __syncthreads();

        for (int s = 0; s < 32; s++) {
            float dAv = sdA[s], dtv = sdt[s];
            float x0 = sx[s][p0], x1 = sx[s][p1];
            float dtx0 = dtv * x0, dtx1 = dtv * x1;
            float a0 = 0.f, a1 = 0.f;
            #pragma unroll
            for (int i = 0; i < 16; i += 4) {
                float4 Bv = *(const float4*)&sB[s][n0 + i];
                float4 Cv = *(const float4*)&sC[s][n0 + i];
                h0[i+0] = dAv*h0[i+0] + dtx0*Bv.x; a0 += h0[i+0]*Cv.x;
                h0[i+1] = dAv*h0[i+1] + dtx0*Bv.y; a0 += h0[i+1]*Cv.y;
                h0[i+2] = dAv*h0[i+2] + dtx0*Bv.z; a0 += h0[i+2]*Cv.z;
                h0[i+3] = dAv*h0[i+3] + dtx0*Bv.w; a0 += h0[i+3]*Cv.w;
                h1[i+0] = dAv*h1[i+0] + dtx1*Bv.x; a1 += h1[i+0]*Cv.x;
                h1[i+1] = dAv*h1[i+1] + dtx1*Bv.y; a1 += h1[i+1]*Cv.y;
                h1[i+2] = dAv*h1[i+2] + dtx1*Bv.z; a1 += h1[i+2]*Cv.z;
                h1[i+3] = dAv*h1[i+3] + dtx1*Bv.w; a1 += h1[i+3]*Cv.w;
            }
            a0 += __shfl_xor_sync(0xffffffffu, a0, 1);
            a0 += __shfl_xor_sync(0xffffffffu, a0, 2);
            a1 += __shfl_xor_sync(0xffffffffu, a1, 1);
            a1 += __shfl_xor_sync(0xffffffffu, a1, 2);
            if (q == 0) {
                size_t ob = (size_t)((b << 11) + l0 + s) * DIi + (hh << 6);
                g_y[ob + p0] = a0 + Dh * x0;
                g_y[ob + p1] = a1 + Dh * x1;
            }
        }
    }
}

// ---------------- 6) gated RMSNorm -> g_nr (tf32) --------------------------
__global__ void gated_norm_kernel(const float* __restrict__ nw) {
    int row = blockIdx.x;
    const float* yr = g_y + (size_t)row * DIi;
    const float* zr = g_zx + (size_t)row * PROJC;
    float* o = g_nr + (size_t)row * DIi;
    int t = threadIdx.x;
    float v[16];
    float ss = 0.f;
    #pragma unroll
    for (int i = 0; i < 4; i++) {
        int c = t * 4 + i * 1024;
        float4 yv = *(const float4*)(yr + c);
        float4 zv = *(const float4*)(zr + c);
        float a0 = yv.x * siluf(zv.x);
        float a1 = yv.y * siluf(zv.y);
        float a2 = yv.z * siluf(zv.z);
        float a3 = yv.w * siluf(zv.w);
        v[i*4+0]=a0; v[i*4+1]=a1; v[i*4+2]=a2; v[i*4+3]=a3;
        ss += a0*a0 + a1*a1 + a2*a2 + a3*a3;
    }
    float total = block_sum_256(ss);
    float scale = rsqrtf(total / (float)DIi + EPSf);
    #pragma unroll
    for (int i = 0; i < 4; i++) {
        int c = t * 4 + i * 1024;
        float4 qv;
        qv.x = tf32r(nw[c+0] * v[i*4+0] * scale);
        qv.y = tf32r(nw[c+1] * v[i*4+1] * scale);
        qv.z = tf32r(nw[c+2] * v[i*4+2] * scale);
        qv.w = tf32r(nw[c+3] * v[i*4+3] * scale);
        *(float4*)(o + c) = qv;
    }
}

// ---------------- launcher -------------------------------------------------
extern "C" void kernel_launch(void* const* d_in, const int* in_sizes, int n_in,
                              void* d_out, int out_size) {
    const float* u          = (const float*)d_in[0];
    const float* ln_w       = (const float*)d_in[1];
    const float* in_proj_w  = (const float*)d_in[2];
    const float* conv_w     = (const float*)d_in[3];
    const float* conv_b     = (const float*)d_in[4];
    const float* dt_bias    = (const float*)d_in[5];
    const float* A_log      = (const float*)d_in[6];
    const float* Dp         = (const float*)d_in[7];
    const float* norm_w     = (const float*)d_in[8];
    const float* out_proj_w = (const float*)d_in[9];
    float* out = (float*)d_out;

    float *hs_p, *zx_p, *nr_p, *w1_p, *w2_p, *pt_p;
    cudaGetSymbolAddress((void**)&hs_p, g_hs);
    cudaGetSymbolAddress((void**)&zx_p, g_zx);
    cudaGetSymbolAddress((void**)&nr_p, g_nr);
    cudaGetSymbolAddress((void**)&w1_p, g_w1);
    cudaGetSymbolAddress((void**)&w2_p, g_w2);
    cudaGetSymbolAddress((void**)&pt_p, g_pt);

    cudaFuncSetAttribute(gemm_wide, cudaFuncAttributeMaxDynamicSharedMemorySize, SMEM_WIDE);

    // 0) round weights to tf32
    {
        int n1 = PROJC * DMd / 4;
        tf32_round4<<<(n1 + 255) / 256, 256>>>((const float4*)in_proj_w, (float4*)w1_p, n1);
        int n2 = DMd * DIi / 4;
        tf32_round4<<<(n2 + 255) / 256, 256>>>((const float4*)out_proj_w, (float4*)w2_p, n2);
    }

    // 1) input rmsnorm (tf32-rounded output)
    rmsnorm_in_kernel<<<ML, 256>>>(u, ln_w);

    // 2) in_proj: (4096,2048) x (8384,2048)^T -> (4096,8384)
    {
        dim3 grid((PROJC + WBN - 1) / WBN, ML / WBM, 1);
        gemm_wide<<<grid, 256, SMEM_WIDE>>>(hs_p, w1_p, zx_p, PROJC, DMd, DMd);
    }

    // 3) conv + silu
    {
        dim3 grid(CONVC / 128, ML);
        conv_silu_kernel<<<grid, 128>>>(conv_w, conv_b);
    }

    // 4) dt / dA
    dt_kernel<<<(ML * Hh) / 256, 256>>>(dt_bias, A_log);

    // 5) scan
    {
        dim3 grid(Hh, Bb);
        scan_kernel<<<grid, 128>>>(Dp);
    }

    // 6) gated rmsnorm (tf32-rounded output)
    gated_norm_kernel<<<ML, 256>>>(norm_w);

    // 7) out_proj split-K=4: (4096,4096) x (2048,4096)^T -> 4 partials
    {
        dim3 grid(DMd / WBN, ML / WBM, 4);
        gemm_wide<<<grid, 256, SMEM_WIDE>>>(nr_p, w2_p, pt_p, DMd, DIi, DIi / 4);
    }

    // 8) reduce partials + residual -> out
    reduce4_kernel<<<(ML * DMd / 4) / 256, 256>>>(u, out);
}